// round 9
// baseline (speedup 1.0000x reference)
#include <cuda_runtime.h>
#include <cstdint>

#define N_CELL 200000
#define N_WELL 2000
#define E_CC   1200000
#define E_CW   200000
#define CF     16
#define WF     8
#define H      128
#define OUT    75
#define WPB    8
#define R      16
#define BMW    ((N_CELL + 31) / 32)

// ---------------- device scratch ----------------
__device__ __align__(16) float g_aggx[(size_t)N_CELL * CF];
__device__ int      g_cnt[N_CELL];
__device__ unsigned g_bm[BMW];
__device__ __align__(16) float g_Ur[(size_t)R * N_WELL * CF];
__device__ __align__(16) float g_Vr[(size_t)R * N_WELL * CF];
__device__ __align__(16) float g_meta[(size_t)R * N_WELL * 4];   // {beta, count, 0, 0}

// fused-weight pipeline
// F rows: [0,16) M1 (Un), [16,32) M2 (Vn), 32 v1 (beta_n), 33 v2 (mask),
//         [34,42) M3 (wx), 42 v3 (const)
__device__ float g_T1[43 * H];
__device__ float g_T2[34 * H];
__device__ float g_F[43 * H];

// grid barrier state (returns to init values after an even number of barriers)
__device__ unsigned g_bar_cnt = 0;
__device__ volatile unsigned g_bar_sense = 0;

__device__ __forceinline__ void red4(float* p, float a, float b, float c, float d) {
    asm volatile("red.global.add.v4.f32 [%0], {%1,%2,%3,%4};"
                 :: "l"(p), "f"(a), "f"(b), "f"(c), "f"(d) : "memory");
}

__device__ __forceinline__ void grid_bar(int nb, unsigned s) {
    __syncthreads();
    if (threadIdx.x == 0) {
        __threadfence();
        unsigned old = atomicAdd(&g_bar_cnt, 1u);
        if (old == (unsigned)(nb - 1)) {
            atomicExch(&g_bar_cnt, 0u);
            __threadfence();
            g_bar_sense = s;
        } else {
            while (g_bar_sense != s) __nanosleep(64);
        }
    }
    __syncthreads();
}

// ---------------- fuse-stage body (block-local) ----------------
// L: 128 floats (scratch or input, read via ldcg), M: [128 x 128] input weight
__device__ __forceinline__ void stage_row(const float* __restrict__ L,
                                          const float* __restrict__ M,
                                          float* __restrict__ dst,
                                          const float* __restrict__ addv,
                                          float* sL, float* sP)
{
    int tid  = threadIdx.x;
    int h    = tid & (H - 1);
    int half = tid >> 7;
    if (half == 0) sL[h] = __ldcg(&L[h]);
    __syncthreads();
    float acc = 0.f;
    int k0 = half * 64;
#pragma unroll 16
    for (int k = 0; k < 64; k++)
        acc += sL[k0 + k] * __ldg(&M[(k0 + k) * H + h]);
    sP[tid] = acc;
    __syncthreads();
    if (half == 0) {
        float v = sP[h] + sP[h + 128];
        if (addv) v += __ldg(&addv[h]);
        dst[h] = v;
    }
    __syncthreads();
}

// ---------------- the single persistent kernel ----------------
__global__ void __launch_bounds__(256, 4) k_all(
    int nb,
    const float* __restrict__ x,        const float* __restrict__ well_x,
    const int* __restrict__ ei,
    const int* __restrict__ ews,        const int* __restrict__ ewd,
    const float* __restrict__ W_cell,   const float* __restrict__ b_cell,
    const float* __restrict__ W_well,   const float* __restrict__ b_well,
    const float* __restrict__ Wl_cc,    const float* __restrict__ bl_cc,
    const float* __restrict__ Wr_cc,
    const float* __restrict__ Wl_cw,    const float* __restrict__ bl_cw,
    const float* __restrict__ Wr_cw,
    const float* __restrict__ Wm1,      const float* __restrict__ bm1,
    const float* __restrict__ Wm2,      const float* __restrict__ bm2,
    float* __restrict__ out)
{
    __shared__ float sL[H];
    __shared__ float sP[256];
    __shared__ __align__(16) float sm[H][WPB];
    __shared__ float sUn[WPB][CF], sVn[WPB][CF], sWX[WPB][WF];
    __shared__ float sb1[WPB], sb2[WPB], sinv[WPB];

    const int tid  = threadIdx.x;
    const int bid  = blockIdx.x;
    const int gtid = bid * 256 + tid;
    const int nthr = nb * 256;
    const float4 z4 = make_float4(0.f, 0.f, 0.f, 0.f);

    // ---------- P0: zero all scratch; blocks <43 also do fuse stage 1 ----------
    for (int i = gtid; i < N_CELL * CF / 4; i += nthr) ((float4*)g_aggx)[i] = z4;
    for (int i = gtid; i < N_CELL; i += nthr)          g_cnt[i] = 0;
    for (int i = gtid; i < BMW; i += nthr)             g_bm[i] = 0u;
    for (int i = gtid; i < R * N_WELL * CF / 4; i += nthr) {
        ((float4*)g_Ur)[i] = z4;
        ((float4*)g_Vr)[i] = z4;
    }
    for (int i = gtid; i < R * N_WELL; i += nthr) ((float4*)g_meta)[i] = z4;

    if (bid < 43) {
        int r = bid;
        const float* L; const float* M; const float* A = nullptr;
        if (r < 16)      { L = W_cell + r * H;        M = Wl_cc; }
        else if (r < 32) { L = W_cell + (r - 16) * H; M = Wr_cc; }
        else if (r == 32){ L = b_cell;                M = Wl_cc; }
        else if (r == 33){ L = b_cell;                M = Wr_cc; A = bl_cc; }
        else if (r < 42) { L = W_well + (r - 34) * H; M = Wr_cw; }
        else             { L = b_well;                M = Wr_cw; A = bl_cw; }
        stage_row(L, M, g_T1 + r * H, A, sL, sP);
    }

    grid_bar(nb, 1u);

    // ---------- P1: mark + cwV + fuse stage 2 ----------
    for (int e = gtid; e < E_CW; e += nthr) {
        int s = __ldg(&ews[e]);
        atomicOr(&g_bm[s >> 5], 1u << (s & 31));
    }
    {
        int rep = bid & (R - 1);
        for (int e = gtid; e < E_CW; e += nthr) {
            int s = __ldg(&ews[e]);
            int w = __ldg(&ewd[e]);
            const float4* xp = (const float4*)(x + (size_t)s * CF);
            float* V = g_Vr + ((size_t)rep * N_WELL + w) * CF;
            float4 b0 = __ldg(xp + 0), b1 = __ldg(xp + 1), b2 = __ldg(xp + 2), b3 = __ldg(xp + 3);
            red4(V + 0,  b0.x, b0.y, b0.z, b0.w);
            red4(V + 4,  b1.x, b1.y, b1.z, b1.w);
            red4(V + 8,  b2.x, b2.y, b2.z, b2.w);
            red4(V + 12, b3.x, b3.y, b3.z, b3.w);
            red4(g_meta + ((size_t)rep * N_WELL + w) * 4, 0.f, 1.f, 0.f, 0.f);
        }
    }
    if (bid < 34)
        stage_row(g_T1 + bid * H, Wl_cw, g_T2 + bid * H, nullptr, sL, sP);

    grid_bar(nb, 0u);

    // ---------- P2: cc scan (2 edges/thread, front-batched) + fuse stage 3 ----
    for (int e = gtid; e < E_CC; e += 2 * nthr) {
        int eb = e + nthr;
        int d0 = __ldg(&ei[E_CC + e]);
        int s0 = __ldg(&ei[e]);
        bool h0 = (__ldcg(&g_bm[d0 >> 5]) >> (d0 & 31)) & 1u;
        int d1 = 0, s1 = 0; bool h1 = false;
        if (eb < E_CC) {
            d1 = __ldg(&ei[E_CC + eb]);
            s1 = __ldg(&ei[eb]);
            h1 = (__ldcg(&g_bm[d1 >> 5]) >> (d1 & 31)) & 1u;
        }
        float4 a0, a1, a2, a3, c0, c1, c2, c3;
        if (h0) {
            const float4* xp = (const float4*)(x + (size_t)s0 * CF);
            a0 = __ldg(xp + 0); a1 = __ldg(xp + 1); a2 = __ldg(xp + 2); a3 = __ldg(xp + 3);
        }
        if (h1) {
            const float4* xp = (const float4*)(x + (size_t)s1 * CF);
            c0 = __ldg(xp + 0); c1 = __ldg(xp + 1); c2 = __ldg(xp + 2); c3 = __ldg(xp + 3);
        }
        if (h0) {
            float* ap = g_aggx + (size_t)d0 * CF;
            red4(ap + 0,  a0.x, a0.y, a0.z, a0.w);
            red4(ap + 4,  a1.x, a1.y, a1.z, a1.w);
            red4(ap + 8,  a2.x, a2.y, a2.z, a2.w);
            red4(ap + 12, a3.x, a3.y, a3.z, a3.w);
            atomicAdd(&g_cnt[d0], 1);
        }
        if (h1) {
            float* ap = g_aggx + (size_t)d1 * CF;
            red4(ap + 0,  c0.x, c0.y, c0.z, c0.w);
            red4(ap + 4,  c1.x, c1.y, c1.z, c1.w);
            red4(ap + 8,  c2.x, c2.y, c2.z, c2.w);
            red4(ap + 12, c3.x, c3.y, c3.z, c3.w);
            atomicAdd(&g_cnt[d1], 1);
        }
    }
    if (bid < 43) {
        const float* L = (bid < 34) ? (g_T2 + bid * H) : (g_T1 + bid * H);
        const float* A = (bid == 42) ? bm1 : nullptr;
        stage_row(L, Wm1, g_F + bid * H, A, sL, sP);
    }

    grid_bar(nb, 1u);

    // ---------- P3: cwU (needs g_cnt, g_aggx) ----------
    {
        int rep = bid & (R - 1);
        for (int e = gtid; e < E_CW; e += nthr) {
            int s = __ldg(&ews[e]);
            int w = __ldg(&ewd[e]);
            int c = __ldcg(&g_cnt[s]);
            float inv = (c > 0) ? (1.f / (float)c) : 0.f;
            const float4* ap = (const float4*)(g_aggx + (size_t)s * CF);
            float4 a0 = __ldcg(ap + 0), a1 = __ldcg(ap + 1),
                   a2 = __ldcg(ap + 2), a3 = __ldcg(ap + 3);
            float* U = g_Ur + ((size_t)rep * N_WELL + w) * CF;
            red4(U + 0,  a0.x * inv, a0.y * inv, a0.z * inv, a0.w * inv);
            red4(U + 4,  a1.x * inv, a1.y * inv, a1.z * inv, a1.w * inv);
            red4(U + 8,  a2.x * inv, a2.y * inv, a2.z * inv, a2.w * inv);
            red4(U + 12, a3.x * inv, a3.y * inv, a3.z * inv, a3.w * inv);
            red4(g_meta + ((size_t)rep * N_WELL + w) * 4, (c > 0) ? 1.f : 0.f, 0.f, 0.f, 0.f);
        }
    }

    grid_bar(nb, 0u);

    // ---------- P4: per-well head (8 wells per task; both 128-halves duplicate) --
    for (int task = bid; task < N_WELL / WPB; task += nb) {
        int h  = tid & (H - 1);
        int w0 = task * WPB;

        if (h < WPB) {
            float beta = 0.f, cw = 0.f;
#pragma unroll
            for (int r = 0; r < R; r++) {
                const float* mp = g_meta + ((size_t)r * N_WELL + (w0 + h)) * 4;
                beta += __ldcg(&mp[0]);
                cw   += __ldcg(&mp[1]);
            }
            float inv = 1.f / fmaxf(cw, 1.f);
            sinv[h] = inv;
            sb1[h]  = beta * inv;
            sb2[h]  = (cw > 0.5f) ? 1.f : 0.f;
        }
        __syncthreads();
        {
            int t = h >> 4, j = h & 15;
            float su = 0.f, svv = 0.f;
#pragma unroll
            for (int r = 0; r < R; r++) {
                size_t off = ((size_t)r * N_WELL + (w0 + t)) * CF + j;
                su  += __ldcg(&g_Ur[off]);
                svv += __ldcg(&g_Vr[off]);
            }
            sUn[t][j] = su * sinv[t];
            sVn[t][j] = svv * sinv[t];
        }
        if (h < WPB * WF) {
            int t = h >> 3, j = h & 7;
            sWX[t][j] = __ldg(&well_x[(w0 + t) * WF + j]);
        }
        __syncthreads();

        float acc[WPB];
        {
            float f1 = __ldcg(&g_F[32 * H + h]);
            float f2 = __ldcg(&g_F[33 * H + h]);
            float f3 = __ldcg(&g_F[42 * H + h]);
#pragma unroll
            for (int t = 0; t < WPB; t++) acc[t] = f3 + sb1[t] * f1 + sb2[t] * f2;
        }
#pragma unroll
        for (int j = 0; j < CF; j++) {
            float m1 = __ldcg(&g_F[j * H + h]);
            float m2 = __ldcg(&g_F[(16 + j) * H + h]);
#pragma unroll
            for (int t = 0; t < WPB; t++) acc[t] += sUn[t][j] * m1 + sVn[t][j] * m2;
        }
#pragma unroll
        for (int j = 0; j < WF; j++) {
            float m3 = __ldcg(&g_F[(34 + j) * H + h]);
#pragma unroll
            for (int t = 0; t < WPB; t++) acc[t] += sWX[t][j] * m3;
        }
#pragma unroll
        for (int t = 0; t < WPB; t++) sm[h][t] = fmaxf(acc[t], 0.f);
        __syncthreads();

        if (h < OUT) {
            float o[WPB];
            float bv = __ldg(&bm2[h]);
#pragma unroll
            for (int t = 0; t < WPB; t++) o[t] = bv;
#pragma unroll 4
            for (int k = 0; k < H; k++) {
                float wm = __ldg(&Wm2[k * OUT + h]);
                float4 p0 = *(const float4*)&sm[k][0];
                float4 p1 = *(const float4*)&sm[k][4];
                o[0] += p0.x * wm;  o[1] += p0.y * wm;
                o[2] += p0.z * wm;  o[3] += p0.w * wm;
                o[4] += p1.x * wm;  o[5] += p1.y * wm;
                o[6] += p1.z * wm;  o[7] += p1.w * wm;
            }
#pragma unroll
            for (int t = 0; t < WPB; t++) out[(w0 + t) * OUT + h] = o[t];
        }
        __syncthreads();
    }
}

// ---------------- launch ----------------
static int g_nb = 0;

extern "C" void kernel_launch(void* const* d_in, const int* in_sizes, int n_in,
                              void* d_out, int out_size)
{
    if (g_nb == 0) {
        int dev = 0;
        cudaGetDevice(&dev);
        cudaDeviceProp prop;
        cudaGetDeviceProperties(&prop, dev);
        int occ = 0;
        cudaOccupancyMaxActiveBlocksPerMultiprocessor(&occ, k_all, 256, 0);
        if (occ < 1) occ = 1;
        if (occ > 4) occ = 4;
        g_nb = prop.multiProcessorCount * occ;
        if (g_nb < 64) g_nb = 64;
        if (g_nb > 1184) g_nb = 1184;
    }

    const float* cell_x  = (const float*)d_in[0];
    const float* well_x  = (const float*)d_in[1];
    const int*   ei_cell = (const int*)  d_in[2];
    const int*   ews     = (const int*)  d_in[3];
    const int*   ewd     = (const int*)  d_in[4];
    const float* W_cell  = (const float*)d_in[5];
    const float* b_cell  = (const float*)d_in[6];
    const float* W_well  = (const float*)d_in[7];
    const float* b_well  = (const float*)d_in[8];
    const float* Wl_cc   = (const float*)d_in[9];
    const float* bl_cc   = (const float*)d_in[10];
    const float* Wr_cc   = (const float*)d_in[11];
    const float* Wl_cw   = (const float*)d_in[12];
    const float* bl_cw   = (const float*)d_in[13];
    const float* Wr_cw   = (const float*)d_in[14];
    const float* W_m1    = (const float*)d_in[15];
    const float* b_m1    = (const float*)d_in[16];
    const float* W_m2    = (const float*)d_in[17];
    const float* b_m2    = (const float*)d_in[18];
    float* out = (float*)d_out;

    k_all<<<g_nb, 256>>>(g_nb,
                         cell_x, well_x, ei_cell, ews, ewd,
                         W_cell, b_cell, W_well, b_well,
                         Wl_cc, bl_cc, Wr_cc,
                         Wl_cw, bl_cw, Wr_cw,
                         W_m1, b_m1, W_m2, b_m2, out);
}

// round 10
// speedup vs baseline: 1.0739x; 1.0739x over previous
#include <cuda_runtime.h>
#include <cstdint>

#define N_CELL 200000
#define N_WELL 2000
#define E_CC   1200000
#define E_CW   200000
#define CF     16
#define WF     8
#define H      128
#define OUT    75
#define WPB    8
#define R      16

// ---------------- device scratch ----------------
__device__ __align__(16) float g_aggx[(size_t)N_CELL * CF];
__device__ int      g_cnt[N_CELL];
__device__ unsigned g_bm[(N_CELL + 31) / 32];
__device__ __align__(16) float g_Ur[(size_t)R * N_WELL * CF];
__device__ __align__(16) float g_Vr[(size_t)R * N_WELL * CF];
__device__ __align__(16) float g_meta[(size_t)R * N_WELL * 4];   // {beta, count, 0, 0}

// fused-weight pipeline
// F rows: [0,16) M1 (Un), [16,32) M2 (Vn), 32 v1 (beta_n), 33 v2 (mask),
//         [34,42) M3 (wx), 42 v3 (const)
__device__ float g_T1[43 * H];
__device__ float g_T2[34 * H];
__device__ float g_F[43 * H];

__device__ __forceinline__ void red4(float* p, float a, float b, float c, float d) {
    asm volatile("red.global.add.v4.f32 [%0], {%1,%2,%3,%4};"
                 :: "l"(p), "f"(a), "f"(b), "f"(c), "f"(d) : "memory");
}
__device__ __forceinline__ void red1u(int* p) {
    asm volatile("red.global.add.u32 [%0], 1;" :: "l"(p) : "memory");
}

// ---------------- zero kernels ----------------
__global__ void k_zero_cell() {
    int i = blockIdx.x * blockDim.x + threadIdx.x;
    if (i < N_CELL * CF / 4) ((float4*)g_aggx)[i] = make_float4(0.f, 0.f, 0.f, 0.f);
    if (i < N_CELL) g_cnt[i] = 0;
    if (i < (N_CELL + 31) / 32) g_bm[i] = 0u;
}
__global__ void k_zero_well() {
    int i = blockIdx.x * blockDim.x + threadIdx.x;
    if (i < R * N_WELL * CF / 4) {
        ((float4*)g_Ur)[i] = make_float4(0.f, 0.f, 0.f, 0.f);
        ((float4*)g_Vr)[i] = make_float4(0.f, 0.f, 0.f, 0.f);
    }
    if (i < R * N_WELL) ((float4*)g_meta)[i] = make_float4(0.f, 0.f, 0.f, 0.f);
}

// ---------------- mark active cells ----------------
__global__ void k_mark(const int* __restrict__ ews) {
    int e = blockIdx.x * blockDim.x + threadIdx.x;
    if (e >= E_CW) return;
    int s = __ldg(&ews[e]);
    atomicOr(&g_bm[s >> 5], 1u << (s & 31));
}

// ---------------- fuse-stage body ----------------
__device__ __forceinline__ void stage_row(const float* __restrict__ L,
                                          const float* __restrict__ M,
                                          float* __restrict__ dst,
                                          const float* __restrict__ addv,
                                          float* sL, float* sP)
{
    int tid  = threadIdx.x;
    int h    = tid & (H - 1);
    int half = tid >> 7;
    if (half == 0) sL[h] = __ldg(&L[h]);
    __syncthreads();
    float acc = 0.f;
    int k0 = half * 64;
#pragma unroll 16
    for (int k = 0; k < 64; k++)
        acc += sL[k0 + k] * __ldg(&M[(k0 + k) * H + h]);
    sP[tid] = acc;
    __syncthreads();
    if (half == 0) {
        float v = sP[h] + sP[h + 128];
        if (addv) v += __ldg(&addv[h]);
        dst[h] = v;
    }
}

__global__ void __launch_bounds__(256) k_f1(
    const float* __restrict__ W_cell, const float* __restrict__ b_cell,
    const float* __restrict__ Wl_cc, const float* __restrict__ Wr_cc,
    const float* __restrict__ bl_cc,
    const float* __restrict__ W_well, const float* __restrict__ b_well,
    const float* __restrict__ Wr_cw, const float* __restrict__ bl_cw)
{
    __shared__ float sL[H];
    __shared__ float sP[256];
    int r = blockIdx.x;
    const float* L; const float* M; const float* A = nullptr;
    if (r < 16)      { L = W_cell + r * H;        M = Wl_cc; }
    else if (r < 32) { L = W_cell + (r - 16) * H; M = Wr_cc; }
    else if (r == 32){ L = b_cell;                M = Wl_cc; }
    else if (r == 33){ L = b_cell;                M = Wr_cc; A = bl_cc; }
    else if (r < 42) { L = W_well + (r - 34) * H; M = Wr_cw; }
    else             { L = b_well;                M = Wr_cw; A = bl_cw; }
    stage_row(L, M, g_T1 + r * H, A, sL, sP);
}

__global__ void __launch_bounds__(256) k_f2(const float* __restrict__ Wl_cw)
{
    __shared__ float sL[H];
    __shared__ float sP[256];
    int r = blockIdx.x;
    stage_row(g_T1 + r * H, Wl_cw, g_T2 + r * H, nullptr, sL, sP);
}

__global__ void __launch_bounds__(256) k_f3(const float* __restrict__ Wm1,
                                            const float* __restrict__ bm1)
{
    __shared__ float sL[H];
    __shared__ float sP[256];
    int r = blockIdx.x;
    const float* L = (r < 34) ? (g_T2 + r * H) : (g_T1 + r * H);
    const float* A = (r == 42) ? bm1 : nullptr;
    stage_row(L, Wm1, g_F + r * H, A, sL, sP);
}

// ---- K3: cc scan, 4 consecutive edges/thread, int4 index loads,
//      conditional gathers front-loaded before any red ----
__global__ void __launch_bounds__(256) k_cc(const int* __restrict__ ei,
                                            const float* __restrict__ x) {
    int t = blockIdx.x * blockDim.x + threadIdx.x;
    if (t >= E_CC / 4) return;

    int4 dv = __ldg((const int4*)(ei + E_CC) + t);   // 4 dsts
    int4 sv = __ldg((const int4*)ei + t);            // 4 srcs
    int d[4] = { dv.x, dv.y, dv.z, dv.w };
    int s[4] = { sv.x, sv.y, sv.z, sv.w };

    bool hit[4];
#pragma unroll
    for (int k = 0; k < 4; k++)
        hit[k] = (__ldg(&g_bm[d[k] >> 5]) >> (d[k] & 31)) & 1u;

    // front-loaded conditional gathers (no reds yet -> loads overlap)
    float4 v[4][4];
#pragma unroll
    for (int k = 0; k < 4; k++) {
        if (hit[k]) {
            const float4* xp = (const float4*)(x + (size_t)s[k] * CF);
            v[k][0] = __ldg(xp + 0);
            v[k][1] = __ldg(xp + 1);
            v[k][2] = __ldg(xp + 2);
            v[k][3] = __ldg(xp + 3);
        }
    }
#pragma unroll
    for (int k = 0; k < 4; k++) {
        if (hit[k]) {
            float* ap = g_aggx + (size_t)d[k] * CF;
            red4(ap + 0,  v[k][0].x, v[k][0].y, v[k][0].z, v[k][0].w);
            red4(ap + 4,  v[k][1].x, v[k][1].y, v[k][1].z, v[k][1].w);
            red4(ap + 8,  v[k][2].x, v[k][2].y, v[k][2].z, v[k][2].w);
            red4(ap + 12, v[k][3].x, v[k][3].y, v[k][3].z, v[k][3].w);
            red1u(&g_cnt[d[k]]);
        }
    }
}

// ---- K4: combined cw scan, 4 edges/thread, int4 index loads ----
__global__ void __launch_bounds__(256) k_cw(const int* __restrict__ ews,
                                            const int* __restrict__ ewd,
                                            const float* __restrict__ x) {
    int t = blockIdx.x * blockDim.x + threadIdx.x;
    if (t >= E_CW / 4) return;
    int rep = blockIdx.x & (R - 1);

    int4 sv = __ldg((const int4*)ews + t);
    int4 wv = __ldg((const int4*)ewd + t);
    int s[4] = { sv.x, sv.y, sv.z, sv.w };
    int w[4] = { wv.x, wv.y, wv.z, wv.w };

    int c[4];
#pragma unroll
    for (int k = 0; k < 4; k++) c[k] = __ldg(&g_cnt[s[k]]);

    // front-load all gathers (8 float4 per edge-pair region)
    float4 a[4][4], b[4][4];
#pragma unroll
    for (int k = 0; k < 4; k++) {
        const float4* ap = (const float4*)(g_aggx + (size_t)s[k] * CF);
        const float4* xp = (const float4*)(x + (size_t)s[k] * CF);
        a[4 - 1 - (3 - k)][0] = __ldg(ap + 0);  // keep simple indexing
        a[k][0] = __ldg(ap + 0); a[k][1] = __ldg(ap + 1);
        a[k][2] = __ldg(ap + 2); a[k][3] = __ldg(ap + 3);
        b[k][0] = __ldg(xp + 0); b[k][1] = __ldg(xp + 1);
        b[k][2] = __ldg(xp + 2); b[k][3] = __ldg(xp + 3);
    }
#pragma unroll
    for (int k = 0; k < 4; k++) {
        float inv = (c[k] > 0) ? (1.f / (float)c[k]) : 0.f;
        float* U = g_Ur + ((size_t)rep * N_WELL + w[k]) * CF;
        float* V = g_Vr + ((size_t)rep * N_WELL + w[k]) * CF;
        red4(U + 0,  a[k][0].x * inv, a[k][0].y * inv, a[k][0].z * inv, a[k][0].w * inv);
        red4(U + 4,  a[k][1].x * inv, a[k][1].y * inv, a[k][1].z * inv, a[k][1].w * inv);
        red4(U + 8,  a[k][2].x * inv, a[k][2].y * inv, a[k][2].z * inv, a[k][2].w * inv);
        red4(U + 12, a[k][3].x * inv, a[k][3].y * inv, a[k][3].z * inv, a[k][3].w * inv);
        red4(V + 0,  b[k][0].x, b[k][0].y, b[k][0].z, b[k][0].w);
        red4(V + 4,  b[k][1].x, b[k][1].y, b[k][1].z, b[k][1].w);
        red4(V + 8,  b[k][2].x, b[k][2].y, b[k][2].z, b[k][2].w);
        red4(V + 12, b[k][3].x, b[k][3].y, b[k][3].z, b[k][3].w);
        red4(g_meta + ((size_t)rep * N_WELL + w[k]) * 4,
             (c[k] > 0) ? 1.f : 0.f, 1.f, 0.f, 0.f);
    }
}

// ---------------- K6: per-well head ----------------
__global__ void __launch_bounds__(H) k_well(
    const float* __restrict__ well_x,
    const float* __restrict__ Wm2, const float* __restrict__ bm2,
    float* __restrict__ out)
{
    __shared__ __align__(16) float sm[H][WPB];
    __shared__ float sUn[WPB][CF], sVn[WPB][CF], sWX[WPB][WF];
    __shared__ float sb1[WPB], sb2[WPB], sinv[WPB];

    int h  = threadIdx.x;
    int w0 = blockIdx.x * WPB;

    if (h < WPB) {
        float beta = 0.f, cw = 0.f;
#pragma unroll
        for (int r = 0; r < R; r++) {
            const float* mp = g_meta + ((size_t)r * N_WELL + (w0 + h)) * 4;
            beta += mp[0];
            cw   += mp[1];
        }
        float inv = 1.f / fmaxf(cw, 1.f);
        sinv[h] = inv;
        sb1[h]  = beta * inv;
        sb2[h]  = (cw > 0.5f) ? 1.f : 0.f;
    }
    __syncthreads();
    {
        int t = h >> 4, j = h & 15;
        float su = 0.f, svv = 0.f;
#pragma unroll
        for (int r = 0; r < R; r++) {
            size_t off = ((size_t)r * N_WELL + (w0 + t)) * CF + j;
            su  += g_Ur[off];
            svv += g_Vr[off];
        }
        sUn[t][j] = su * sinv[t];
        sVn[t][j] = svv * sinv[t];
    }
    if (h < WPB * WF) {
        int t = h >> 3, j = h & 7;
        sWX[t][j] = __ldg(&well_x[(w0 + t) * WF + j]);
    }
    __syncthreads();

    float acc[WPB];
    {
        float f1 = g_F[32 * H + h], f2 = g_F[33 * H + h], f3 = g_F[42 * H + h];
#pragma unroll
        for (int t = 0; t < WPB; t++) acc[t] = f3 + sb1[t] * f1 + sb2[t] * f2;
    }
#pragma unroll
    for (int j = 0; j < CF; j++) {
        float m1 = g_F[j * H + h];
        float m2 = g_F[(16 + j) * H + h];
#pragma unroll
        for (int t = 0; t < WPB; t++) acc[t] += sUn[t][j] * m1 + sVn[t][j] * m2;
    }
#pragma unroll
    for (int j = 0; j < WF; j++) {
        float m3 = g_F[(34 + j) * H + h];
#pragma unroll
        for (int t = 0; t < WPB; t++) acc[t] += sWX[t][j] * m3;
    }
#pragma unroll
    for (int t = 0; t < WPB; t++) sm[h][t] = fmaxf(acc[t], 0.f);
    __syncthreads();

    if (h < OUT) {
        float o[WPB];
        float bv = __ldg(&bm2[h]);
#pragma unroll
        for (int t = 0; t < WPB; t++) o[t] = bv;
#pragma unroll 4
        for (int k = 0; k < H; k++) {
            float wm = __ldg(&Wm2[k * OUT + h]);
            float4 p0 = *(const float4*)&sm[k][0];
            float4 p1 = *(const float4*)&sm[k][4];
            o[0] += p0.x * wm;  o[1] += p0.y * wm;
            o[2] += p0.z * wm;  o[3] += p0.w * wm;
            o[4] += p1.x * wm;  o[5] += p1.y * wm;
            o[6] += p1.z * wm;  o[7] += p1.w * wm;
        }
#pragma unroll
        for (int t = 0; t < WPB; t++) out[(w0 + t) * OUT + h] = o[t];
    }
}

// ---------------- launch (fork-join over 2 streams, capture-safe) ---------
static cudaStream_t s1;
static cudaEvent_t evRoot, evW;
static bool g_host_init = false;

extern "C" void kernel_launch(void* const* d_in, const int* in_sizes, int n_in,
                              void* d_out, int out_size)
{
    if (!g_host_init) {
        cudaStreamCreateWithFlags(&s1, cudaStreamNonBlocking);
        cudaEventCreateWithFlags(&evRoot, cudaEventDisableTiming);
        cudaEventCreateWithFlags(&evW, cudaEventDisableTiming);
        g_host_init = true;
    }

    const float* cell_x  = (const float*)d_in[0];
    const float* well_x  = (const float*)d_in[1];
    const int*   ei_cell = (const int*)  d_in[2];
    const int*   ews     = (const int*)  d_in[3];
    const int*   ewd     = (const int*)  d_in[4];
    const float* W_cell  = (const float*)d_in[5];
    const float* b_cell  = (const float*)d_in[6];
    const float* W_well  = (const float*)d_in[7];
    const float* b_well  = (const float*)d_in[8];
    const float* Wl_cc   = (const float*)d_in[9];
    const float* bl_cc   = (const float*)d_in[10];
    const float* Wr_cc   = (const float*)d_in[11];
    const float* Wl_cw   = (const float*)d_in[12];
    const float* bl_cw   = (const float*)d_in[13];
    const float* Wr_cw   = (const float*)d_in[14];
    const float* W_m1    = (const float*)d_in[15];
    const float* b_m1    = (const float*)d_in[16];
    const float* W_m2    = (const float*)d_in[17];
    const float* b_m2    = (const float*)d_in[18];
    float* out = (float*)d_out;

    // fork
    cudaEventRecord(evRoot, 0);
    cudaStreamWaitEvent(s1, evRoot, 0);

    // side stream: fuse chain + well-accumulator zeroing
    k_f1<<<43, 256, 0, s1>>>(W_cell, b_cell, Wl_cc, Wr_cc, bl_cc, W_well, b_well, Wr_cw, bl_cw);
    k_f2<<<34, 256, 0, s1>>>(Wl_cw);
    k_f3<<<43, 256, 0, s1>>>(W_m1, b_m1);
    k_zero_well<<<(R * N_WELL * CF / 4 + 255) / 256, 256, 0, s1>>>();
    cudaEventRecord(evW, s1);

    // main stream: critical path
    k_zero_cell<<<(N_CELL * CF / 4 + 255) / 256, 256>>>();
    k_mark<<<(E_CW + 255) / 256, 256>>>(ews);
    k_cc<<<(E_CC / 4 + 255) / 256, 256>>>(ei_cell, cell_x);
    cudaStreamWaitEvent(0, evW, 0);
    k_cw<<<(E_CW / 4 + 255) / 256, 256>>>(ews, ewd, cell_x);
    k_well<<<N_WELL / WPB, H>>>(well_x, W_m2, b_m2, out);
}

// round 11
// speedup vs baseline: 1.1668x; 1.0865x over previous
#include <cuda_runtime.h>
#include <cstdint>

#define N_CELL 200000
#define N_WELL 2000
#define E_CC   1200000
#define E_CW   200000
#define CF     16
#define WF     8
#define H      128
#define OUT    75
#define WPB    8
#define R      16

// ---------------- device scratch ----------------
__device__ __align__(16) float g_aggx[(size_t)N_CELL * CF];
__device__ int      g_cnt[N_CELL];
__device__ unsigned g_bm[(N_CELL + 31) / 32];
__device__ __align__(16) float g_Ur[(size_t)R * N_WELL * CF];
__device__ __align__(16) float g_Vr[(size_t)R * N_WELL * CF];
__device__ __align__(16) float g_meta[(size_t)R * N_WELL * 4];   // {beta, count, 0, 0}

// fused-weight pipeline
// F rows: [0,16) M1 (Un), [16,32) M2 (Vn), 32 v1 (beta_n), 33 v2 (mask),
//         [34,42) M3 (wx), 42 v3 (const)
__device__ float g_T1[43 * H];
__device__ float g_T2[34 * H];
__device__ float g_F[43 * H];

__device__ __forceinline__ void red4(float* p, float a, float b, float c, float d) {
    asm volatile("red.global.add.v4.f32 [%0], {%1,%2,%3,%4};"
                 :: "l"(p), "f"(a), "f"(b), "f"(c), "f"(d) : "memory");
}

// ---------------- zero kernels ----------------
__global__ void k_zero_cell() {
    int i = blockIdx.x * blockDim.x + threadIdx.x;
    if (i < N_CELL * CF / 4) ((float4*)g_aggx)[i] = make_float4(0.f, 0.f, 0.f, 0.f);
    if (i < N_CELL) g_cnt[i] = 0;
    if (i < (N_CELL + 31) / 32) g_bm[i] = 0u;
}
__global__ void k_zero_well() {
    int i = blockIdx.x * blockDim.x + threadIdx.x;
    if (i < R * N_WELL * CF / 4) {
        ((float4*)g_Ur)[i] = make_float4(0.f, 0.f, 0.f, 0.f);
        ((float4*)g_Vr)[i] = make_float4(0.f, 0.f, 0.f, 0.f);
    }
    if (i < R * N_WELL) ((float4*)g_meta)[i] = make_float4(0.f, 0.f, 0.f, 0.f);
}

// ---------------- mark active cells ----------------
__global__ void k_mark(const int* __restrict__ ews) {
    int e = blockIdx.x * blockDim.x + threadIdx.x;
    if (e >= E_CW) return;
    int s = __ldg(&ews[e]);
    atomicOr(&g_bm[s >> 5], 1u << (s & 31));
}

// ---------------- fuse-stage body ----------------
__device__ __forceinline__ void stage_row(const float* __restrict__ L,
                                          const float* __restrict__ M,
                                          float* __restrict__ dst,
                                          const float* __restrict__ addv,
                                          float* sL, float* sP)
{
    int tid  = threadIdx.x;
    int h    = tid & (H - 1);
    int half = tid >> 7;
    if (half == 0) sL[h] = __ldg(&L[h]);
    __syncthreads();
    float acc = 0.f;
    int k0 = half * 64;
#pragma unroll 16
    for (int k = 0; k < 64; k++)
        acc += sL[k0 + k] * __ldg(&M[(k0 + k) * H + h]);
    sP[tid] = acc;
    __syncthreads();
    if (half == 0) {
        float v = sP[h] + sP[h + 128];
        if (addv) v += __ldg(&addv[h]);
        dst[h] = v;
    }
}

__global__ void __launch_bounds__(256) k_f1(
    const float* __restrict__ W_cell, const float* __restrict__ b_cell,
    const float* __restrict__ Wl_cc, const float* __restrict__ Wr_cc,
    const float* __restrict__ bl_cc,
    const float* __restrict__ W_well, const float* __restrict__ b_well,
    const float* __restrict__ Wr_cw, const float* __restrict__ bl_cw)
{
    __shared__ float sL[H];
    __shared__ float sP[256];
    int r = blockIdx.x;
    const float* L; const float* M; const float* A = nullptr;
    if (r < 16)      { L = W_cell + r * H;        M = Wl_cc; }
    else if (r < 32) { L = W_cell + (r - 16) * H; M = Wr_cc; }
    else if (r == 32){ L = b_cell;                M = Wl_cc; }
    else if (r == 33){ L = b_cell;                M = Wr_cc; A = bl_cc; }
    else if (r < 42) { L = W_well + (r - 34) * H; M = Wr_cw; }
    else             { L = b_well;                M = Wr_cw; A = bl_cw; }
    stage_row(L, M, g_T1 + r * H, A, sL, sP);
}

__global__ void __launch_bounds__(256) k_f2(const float* __restrict__ Wl_cw)
{
    __shared__ float sL[H];
    __shared__ float sP[256];
    int r = blockIdx.x;
    stage_row(g_T1 + r * H, Wl_cw, g_T2 + r * H, nullptr, sL, sP);
}

__global__ void __launch_bounds__(256) k_f3(const float* __restrict__ Wm1,
                                            const float* __restrict__ bm1)
{
    __shared__ float sL[H];
    __shared__ float sP[256];
    int r = blockIdx.x;
    const float* L = (r < 34) ? (g_T2 + r * H) : (g_T1 + r * H);
    const float* A = (r == 42) ? bm1 : nullptr;
    stage_row(L, Wm1, g_F + r * H, A, sL, sP);
}

// ---- K3: cc scan, 2 consecutive edges/thread, int2 index loads,
//      conditional gathers front-loaded before any red ----
__global__ void __launch_bounds__(256) k_cc(const int* __restrict__ ei,
                                            const float* __restrict__ x) {
    int t = blockIdx.x * blockDim.x + threadIdx.x;
    if (t >= E_CC / 2) return;

    int2 dv = __ldg((const int2*)(ei + E_CC) + t);   // 2 dsts
    int2 sv = __ldg((const int2*)ei + t);            // 2 srcs

    bool h0 = (__ldg(&g_bm[dv.x >> 5]) >> (dv.x & 31)) & 1u;
    bool h1 = (__ldg(&g_bm[dv.y >> 5]) >> (dv.y & 31)) & 1u;

    float4 a0, a1, a2, a3, c0, c1, c2, c3;
    if (h0) {
        const float4* xp = (const float4*)(x + (size_t)sv.x * CF);
        a0 = __ldg(xp + 0); a1 = __ldg(xp + 1); a2 = __ldg(xp + 2); a3 = __ldg(xp + 3);
    }
    if (h1) {
        const float4* xp = (const float4*)(x + (size_t)sv.y * CF);
        c0 = __ldg(xp + 0); c1 = __ldg(xp + 1); c2 = __ldg(xp + 2); c3 = __ldg(xp + 3);
    }
    if (h0) {
        float* ap = g_aggx + (size_t)dv.x * CF;
        red4(ap + 0,  a0.x, a0.y, a0.z, a0.w);
        red4(ap + 4,  a1.x, a1.y, a1.z, a1.w);
        red4(ap + 8,  a2.x, a2.y, a2.z, a2.w);
        red4(ap + 12, a3.x, a3.y, a3.z, a3.w);
        atomicAdd(&g_cnt[dv.x], 1);
    }
    if (h1) {
        float* ap = g_aggx + (size_t)dv.y * CF;
        red4(ap + 0,  c0.x, c0.y, c0.z, c0.w);
        red4(ap + 4,  c1.x, c1.y, c1.z, c1.w);
        red4(ap + 8,  c2.x, c2.y, c2.z, c2.w);
        red4(ap + 12, c3.x, c3.y, c3.z, c3.w);
        atomicAdd(&g_cnt[dv.y], 1);
    }
}

// ---------------- K4: combined cw scan (1 edge/thread, as R5) ----------------
__global__ void k_cw(const int* __restrict__ ews, const int* __restrict__ ewd,
                     const float* __restrict__ x) {
    int e = blockIdx.x * blockDim.x + threadIdx.x;
    if (e >= E_CW) return;
    int rep = blockIdx.x & (R - 1);
    int s = __ldg(&ews[e]);
    int w = __ldg(&ewd[e]);
    int c = g_cnt[s];
    float inv = (c > 0) ? (1.f / (float)c) : 0.f;
    const float4* ap = (const float4*)(g_aggx + (size_t)s * CF);
    const float4* xp = (const float4*)(x + (size_t)s * CF);
    float* U = g_Ur + ((size_t)rep * N_WELL + w) * CF;
    float* V = g_Vr + ((size_t)rep * N_WELL + w) * CF;
    float4 a0 = ap[0], a1 = ap[1], a2 = ap[2], a3 = ap[3];
    red4(U + 0,  a0.x * inv, a0.y * inv, a0.z * inv, a0.w * inv);
    red4(U + 4,  a1.x * inv, a1.y * inv, a1.z * inv, a1.w * inv);
    red4(U + 8,  a2.x * inv, a2.y * inv, a2.z * inv, a2.w * inv);
    red4(U + 12, a3.x * inv, a3.y * inv, a3.z * inv, a3.w * inv);
    float4 b0 = __ldg(xp + 0), b1 = __ldg(xp + 1), b2 = __ldg(xp + 2), b3 = __ldg(xp + 3);
    red4(V + 0,  b0.x, b0.y, b0.z, b0.w);
    red4(V + 4,  b1.x, b1.y, b1.z, b1.w);
    red4(V + 8,  b2.x, b2.y, b2.z, b2.w);
    red4(V + 12, b3.x, b3.y, b3.z, b3.w);
    red4(g_meta + ((size_t)rep * N_WELL + w) * 4, (c > 0) ? 1.f : 0.f, 1.f, 0.f, 0.f);
}

// ---------------- K6: per-well head ----------------
__global__ void __launch_bounds__(H) k_well(
    const float* __restrict__ well_x,
    const float* __restrict__ Wm2, const float* __restrict__ bm2,
    float* __restrict__ out)
{
    __shared__ __align__(16) float sm[H][WPB];
    __shared__ float sUn[WPB][CF], sVn[WPB][CF], sWX[WPB][WF];
    __shared__ float sb1[WPB], sb2[WPB], sinv[WPB];

    int h  = threadIdx.x;
    int w0 = blockIdx.x * WPB;

    if (h < WPB) {
        float beta = 0.f, cw = 0.f;
#pragma unroll
        for (int r = 0; r < R; r++) {
            const float* mp = g_meta + ((size_t)r * N_WELL + (w0 + h)) * 4;
            beta += mp[0];
            cw   += mp[1];
        }
        float inv = 1.f / fmaxf(cw, 1.f);
        sinv[h] = inv;
        sb1[h]  = beta * inv;
        sb2[h]  = (cw > 0.5f) ? 1.f : 0.f;
    }
    __syncthreads();
    {
        int t = h >> 4, j = h & 15;
        float su = 0.f, svv = 0.f;
#pragma unroll
        for (int r = 0; r < R; r++) {
            size_t off = ((size_t)r * N_WELL + (w0 + t)) * CF + j;
            su  += g_Ur[off];
            svv += g_Vr[off];
        }
        sUn[t][j] = su * sinv[t];
        sVn[t][j] = svv * sinv[t];
    }
    if (h < WPB * WF) {
        int t = h >> 3, j = h & 7;
        sWX[t][j] = __ldg(&well_x[(w0 + t) * WF + j]);
    }
    __syncthreads();

    float acc[WPB];
    {
        float f1 = g_F[32 * H + h], f2 = g_F[33 * H + h], f3 = g_F[42 * H + h];
#pragma unroll
        for (int t = 0; t < WPB; t++) acc[t] = f3 + sb1[t] * f1 + sb2[t] * f2;
    }
#pragma unroll
    for (int j = 0; j < CF; j++) {
        float m1 = g_F[j * H + h];
        float m2 = g_F[(16 + j) * H + h];
#pragma unroll
        for (int t = 0; t < WPB; t++) acc[t] += sUn[t][j] * m1 + sVn[t][j] * m2;
    }
#pragma unroll
    for (int j = 0; j < WF; j++) {
        float m3 = g_F[(34 + j) * H + h];
#pragma unroll
        for (int t = 0; t < WPB; t++) acc[t] += sWX[t][j] * m3;
    }
#pragma unroll
    for (int t = 0; t < WPB; t++) sm[h][t] = fmaxf(acc[t], 0.f);
    __syncthreads();

    if (h < OUT) {
        float o[WPB];
        float bv = __ldg(&bm2[h]);
#pragma unroll
        for (int t = 0; t < WPB; t++) o[t] = bv;
#pragma unroll 4
        for (int k = 0; k < H; k++) {
            float wm = __ldg(&Wm2[k * OUT + h]);
            float4 p0 = *(const float4*)&sm[k][0];
            float4 p1 = *(const float4*)&sm[k][4];
            o[0] += p0.x * wm;  o[1] += p0.y * wm;
            o[2] += p0.z * wm;  o[3] += p0.w * wm;
            o[4] += p1.x * wm;  o[5] += p1.y * wm;
            o[6] += p1.z * wm;  o[7] += p1.w * wm;
        }
#pragma unroll
        for (int t = 0; t < WPB; t++) out[(w0 + t) * OUT + h] = o[t];
    }
}

// ---------------- launch (fork-join over 2 streams, capture-safe) ---------
static cudaStream_t s1;
static cudaEvent_t evRoot, evW;
static bool g_host_init = false;

extern "C" void kernel_launch(void* const* d_in, const int* in_sizes, int n_in,
                              void* d_out, int out_size)
{
    if (!g_host_init) {
        cudaStreamCreateWithFlags(&s1, cudaStreamNonBlocking);
        cudaEventCreateWithFlags(&evRoot, cudaEventDisableTiming);
        cudaEventCreateWithFlags(&evW, cudaEventDisableTiming);
        g_host_init = true;
    }

    const float* cell_x  = (const float*)d_in[0];
    const float* well_x  = (const float*)d_in[1];
    const int*   ei_cell = (const int*)  d_in[2];
    const int*   ews     = (const int*)  d_in[3];
    const int*   ewd     = (const int*)  d_in[4];
    const float* W_cell  = (const float*)d_in[5];
    const float* b_cell  = (const float*)d_in[6];
    const float* W_well  = (const float*)d_in[7];
    const float* b_well  = (const float*)d_in[8];
    const float* Wl_cc   = (const float*)d_in[9];
    const float* bl_cc   = (const float*)d_in[10];
    const float* Wr_cc   = (const float*)d_in[11];
    const float* Wl_cw   = (const float*)d_in[12];
    const float* bl_cw   = (const float*)d_in[13];
    const float* Wr_cw   = (const float*)d_in[14];
    const float* W_m1    = (const float*)d_in[15];
    const float* b_m1    = (const float*)d_in[16];
    const float* W_m2    = (const float*)d_in[17];
    const float* b_m2    = (const float*)d_in[18];
    float* out = (float*)d_out;

    // fork
    cudaEventRecord(evRoot, 0);
    cudaStreamWaitEvent(s1, evRoot, 0);

    // side stream: fuse chain + well-accumulator zeroing
    k_f1<<<43, 256, 0, s1>>>(W_cell, b_cell, Wl_cc, Wr_cc, bl_cc, W_well, b_well, Wr_cw, bl_cw);
    k_f2<<<34, 256, 0, s1>>>(Wl_cw);
    k_f3<<<43, 256, 0, s1>>>(W_m1, b_m1);
    k_zero_well<<<(R * N_WELL * CF / 4 + 255) / 256, 256, 0, s1>>>();
    cudaEventRecord(evW, s1);

    // main stream: critical path
    k_zero_cell<<<(N_CELL * CF / 4 + 255) / 256, 256>>>();
    k_mark<<<(E_CW + 255) / 256, 256>>>(ews);
    k_cc<<<(E_CC / 2 + 255) / 256, 256>>>(ei_cell, cell_x);
    cudaStreamWaitEvent(0, evW, 0);
    k_cw<<<(E_CW + 255) / 256, 256>>>(ews, ewd, cell_x);
    k_well<<<N_WELL / WPB, H>>>(well_x, W_m2, b_m2, out);
}

// round 12
// speedup vs baseline: 1.2386x; 1.0615x over previous
#include <cuda_runtime.h>
#include <cstdint>

#define N_CELL 200000
#define N_WELL 2000
#define E_CC   1200000
#define E_CW   200000
#define CF     16
#define WF     8
#define H      128
#define OUT    75
#define WPB    8
#define R      16

// ---------------- device scratch ----------------
__device__ __align__(16) float g_aggx[(size_t)N_CELL * CF];
__device__ int      g_cnt[N_CELL];
__device__ unsigned g_bm[(N_CELL + 31) / 32];
__device__ __align__(16) float g_Ur[(size_t)R * N_WELL * CF];
__device__ __align__(16) float g_Vr[(size_t)R * N_WELL * CF];
__device__ __align__(16) float g_meta[(size_t)R * N_WELL * 4];   // {beta, count, 0, 0}

// fused-weight table
// F rows: [0,16) M1 (Un), [16,32) M2 (Vn), 32 v1 (beta_n), 33 v2 (mask),
//         [34,42) M3 (wx), 42 v3 (const)
__device__ float g_F[43 * H];

__device__ __forceinline__ void red4(float* p, float a, float b, float c, float d) {
    asm volatile("red.global.add.v4.f32 [%0], {%1,%2,%3,%4};"
                 :: "l"(p), "f"(a), "f"(b), "f"(c), "f"(d) : "memory");
}

// ---------------- zero everything (one kernel) ----------------
__global__ void k_zero_all() {
    int i = blockIdx.x * blockDim.x + threadIdx.x;
    if (i < N_CELL * CF / 4) ((float4*)g_aggx)[i] = make_float4(0.f, 0.f, 0.f, 0.f);
    if (i < N_CELL) g_cnt[i] = 0;
    if (i < (N_CELL + 31) / 32) g_bm[i] = 0u;
    if (i < R * N_WELL * CF / 4) {
        ((float4*)g_Ur)[i] = make_float4(0.f, 0.f, 0.f, 0.f);
        ((float4*)g_Vr)[i] = make_float4(0.f, 0.f, 0.f, 0.f);
    }
    if (i < R * N_WELL) ((float4*)g_meta)[i] = make_float4(0.f, 0.f, 0.f, 0.f);
}

// ---------------- mark active cells ----------------
__global__ void k_mark(const int* __restrict__ ews) {
    int e = blockIdx.x * blockDim.x + threadIdx.x;
    if (e >= E_CW) return;
    int s = __ldg(&ews[e]);
    atomicOr(&g_bm[s >> 5], 1u << (s & 31));
}

// ---------------- single-kernel fuse chain (block-local row pipeline) -------
// Each block r carries row r through: [stage A] x M_A, [stage B: r<34] x Wl_cw,
// [stage C] x Wm1, writing only g_F[r].
__device__ __forceinline__ void mmrow(const float* sIn, const float* __restrict__ M,
                                      float* sOut, float* gOut,
                                      const float* __restrict__ addv, float* sP)
{
    int tid  = threadIdx.x;
    int h    = tid & (H - 1);
    int half = tid >> 7;
    float acc = 0.f;
    int k0 = half * 64;
#pragma unroll 16
    for (int k = 0; k < 64; k++)
        acc += sIn[k0 + k] * __ldg(&M[(k0 + k) * H + h]);
    __syncthreads();          // prior consumers of sP done
    sP[tid] = acc;
    __syncthreads();
    if (half == 0) {
        float v = sP[h] + sP[h + 128];
        if (addv) v += __ldg(&addv[h]);
        if (sOut) sOut[h] = v;
        if (gOut) gOut[h] = v;
    }
    __syncthreads();
}

__global__ void __launch_bounds__(256) k_fuse(
    const float* __restrict__ W_cell, const float* __restrict__ b_cell,
    const float* __restrict__ Wl_cc, const float* __restrict__ Wr_cc,
    const float* __restrict__ bl_cc,
    const float* __restrict__ W_well, const float* __restrict__ b_well,
    const float* __restrict__ Wl_cw, const float* __restrict__ bl_cw,
    const float* __restrict__ Wr_cw,
    const float* __restrict__ Wm1,   const float* __restrict__ bm1)
{
    __shared__ float sA[H], sB[H], sP[256];
    int r   = blockIdx.x;
    int tid = threadIdx.x;
    int h   = tid & (H - 1);

    // stage A operands
    const float* L; const float* M; const float* A1 = nullptr;
    if (r < 16)      { L = W_cell + r * H;        M = Wl_cc; }
    else if (r < 32) { L = W_cell + (r - 16) * H; M = Wr_cc; }
    else if (r == 32){ L = b_cell;                M = Wl_cc; }
    else if (r == 33){ L = b_cell;                M = Wr_cc; A1 = bl_cc; }
    else if (r < 42) { L = W_well + (r - 34) * H; M = Wr_cw; }
    else             { L = b_well;                M = Wr_cw; A1 = bl_cw; }

    if (tid < H) sA[h] = __ldg(&L[h]);
    __syncthreads();

    // stage A: sB = sA @ M (+A1)
    mmrow(sA, M, sB, nullptr, A1, sP);

    // stage B (cc-chain rows only): sA = sB @ Wl_cw
    const float* last = sB;
    if (r < 34) {
        mmrow(sB, Wl_cw, sA, nullptr, nullptr, sP);
        last = sA;
    }

    // stage C: g_F[r] = last @ Wm1 (+bm1 on the constant row)
    mmrow(last, Wm1, nullptr, g_F + r * H, (r == 42) ? bm1 : nullptr, sP);
}

// ---- K3: cc scan, 2 consecutive edges/thread, int2 index loads,
//      conditional gathers front-loaded before any red ----
__global__ void __launch_bounds__(256) k_cc(const int* __restrict__ ei,
                                            const float* __restrict__ x) {
    int t = blockIdx.x * blockDim.x + threadIdx.x;
    if (t >= E_CC / 2) return;

    int2 dv = __ldg((const int2*)(ei + E_CC) + t);   // 2 dsts
    int2 sv = __ldg((const int2*)ei + t);            // 2 srcs

    bool h0 = (__ldg(&g_bm[dv.x >> 5]) >> (dv.x & 31)) & 1u;
    bool h1 = (__ldg(&g_bm[dv.y >> 5]) >> (dv.y & 31)) & 1u;

    float4 a0, a1, a2, a3, c0, c1, c2, c3;
    if (h0) {
        const float4* xp = (const float4*)(x + (size_t)sv.x * CF);
        a0 = __ldg(xp + 0); a1 = __ldg(xp + 1); a2 = __ldg(xp + 2); a3 = __ldg(xp + 3);
    }
    if (h1) {
        const float4* xp = (const float4*)(x + (size_t)sv.y * CF);
        c0 = __ldg(xp + 0); c1 = __ldg(xp + 1); c2 = __ldg(xp + 2); c3 = __ldg(xp + 3);
    }
    if (h0) {
        float* ap = g_aggx + (size_t)dv.x * CF;
        red4(ap + 0,  a0.x, a0.y, a0.z, a0.w);
        red4(ap + 4,  a1.x, a1.y, a1.z, a1.w);
        red4(ap + 8,  a2.x, a2.y, a2.z, a2.w);
        red4(ap + 12, a3.x, a3.y, a3.z, a3.w);
        atomicAdd(&g_cnt[dv.x], 1);
    }
    if (h1) {
        float* ap = g_aggx + (size_t)dv.y * CF;
        red4(ap + 0,  c0.x, c0.y, c0.z, c0.w);
        red4(ap + 4,  c1.x, c1.y, c1.z, c1.w);
        red4(ap + 8,  c2.x, c2.y, c2.z, c2.w);
        red4(ap + 12, c3.x, c3.y, c3.z, c3.w);
        atomicAdd(&g_cnt[dv.y], 1);
    }
}

// ---------------- K4: combined cw scan (1 edge/thread) ----------------
__global__ void k_cw(const int* __restrict__ ews, const int* __restrict__ ewd,
                     const float* __restrict__ x) {
    int e = blockIdx.x * blockDim.x + threadIdx.x;
    if (e >= E_CW) return;
    int rep = blockIdx.x & (R - 1);
    int s = __ldg(&ews[e]);
    int w = __ldg(&ewd[e]);
    int c = g_cnt[s];
    float inv = (c > 0) ? (1.f / (float)c) : 0.f;
    const float4* ap = (const float4*)(g_aggx + (size_t)s * CF);
    const float4* xp = (const float4*)(x + (size_t)s * CF);
    float* U = g_Ur + ((size_t)rep * N_WELL + w) * CF;
    float* V = g_Vr + ((size_t)rep * N_WELL + w) * CF;
    float4 a0 = ap[0], a1 = ap[1], a2 = ap[2], a3 = ap[3];
    red4(U + 0,  a0.x * inv, a0.y * inv, a0.z * inv, a0.w * inv);
    red4(U + 4,  a1.x * inv, a1.y * inv, a1.z * inv, a1.w * inv);
    red4(U + 8,  a2.x * inv, a2.y * inv, a2.z * inv, a2.w * inv);
    red4(U + 12, a3.x * inv, a3.y * inv, a3.z * inv, a3.w * inv);
    float4 b0 = __ldg(xp + 0), b1 = __ldg(xp + 1), b2 = __ldg(xp + 2), b3 = __ldg(xp + 3);
    red4(V + 0,  b0.x, b0.y, b0.z, b0.w);
    red4(V + 4,  b1.x, b1.y, b1.z, b1.w);
    red4(V + 8,  b2.x, b2.y, b2.z, b2.w);
    red4(V + 12, b3.x, b3.y, b3.z, b3.w);
    red4(g_meta + ((size_t)rep * N_WELL + w) * 4, (c > 0) ? 1.f : 0.f, 1.f, 0.f, 0.f);
}

// ---------------- K6: per-well head ----------------
__global__ void __launch_bounds__(H) k_well(
    const float* __restrict__ well_x,
    const float* __restrict__ Wm2, const float* __restrict__ bm2,
    float* __restrict__ out)
{
    __shared__ __align__(16) float sm[H][WPB];
    __shared__ float sUn[WPB][CF], sVn[WPB][CF], sWX[WPB][WF];
    __shared__ float sb1[WPB], sb2[WPB], sinv[WPB];

    int h  = threadIdx.x;
    int w0 = blockIdx.x * WPB;

    if (h < WPB) {
        float beta = 0.f, cw = 0.f;
#pragma unroll
        for (int r = 0; r < R; r++) {
            const float* mp = g_meta + ((size_t)r * N_WELL + (w0 + h)) * 4;
            beta += mp[0];
            cw   += mp[1];
        }
        float inv = 1.f / fmaxf(cw, 1.f);
        sinv[h] = inv;
        sb1[h]  = beta * inv;
        sb2[h]  = (cw > 0.5f) ? 1.f : 0.f;
    }
    __syncthreads();
    {
        int t = h >> 4, j = h & 15;
        float su = 0.f, svv = 0.f;
#pragma unroll
        for (int r = 0; r < R; r++) {
            size_t off = ((size_t)r * N_WELL + (w0 + t)) * CF + j;
            su  += g_Ur[off];
            svv += g_Vr[off];
        }
        sUn[t][j] = su * sinv[t];
        sVn[t][j] = svv * sinv[t];
    }
    if (h < WPB * WF) {
        int t = h >> 3, j = h & 7;
        sWX[t][j] = __ldg(&well_x[(w0 + t) * WF + j]);
    }
    __syncthreads();

    float acc[WPB];
    {
        float f1 = g_F[32 * H + h], f2 = g_F[33 * H + h], f3 = g_F[42 * H + h];
#pragma unroll
        for (int t = 0; t < WPB; t++) acc[t] = f3 + sb1[t] * f1 + sb2[t] * f2;
    }
#pragma unroll
    for (int j = 0; j < CF; j++) {
        float m1 = g_F[j * H + h];
        float m2 = g_F[(16 + j) * H + h];
#pragma unroll
        for (int t = 0; t < WPB; t++) acc[t] += sUn[t][j] * m1 + sVn[t][j] * m2;
    }
#pragma unroll
    for (int j = 0; j < WF; j++) {
        float m3 = g_F[(34 + j) * H + h];
#pragma unroll
        for (int t = 0; t < WPB; t++) acc[t] += sWX[t][j] * m3;
    }
#pragma unroll
    for (int t = 0; t < WPB; t++) sm[h][t] = fmaxf(acc[t], 0.f);
    __syncthreads();

    if (h < OUT) {
        float o[WPB];
        float bv = __ldg(&bm2[h]);
#pragma unroll
        for (int t = 0; t < WPB; t++) o[t] = bv;
#pragma unroll 4
        for (int k = 0; k < H; k++) {
            float wm = __ldg(&Wm2[k * OUT + h]);
            float4 p0 = *(const float4*)&sm[k][0];
            float4 p1 = *(const float4*)&sm[k][4];
            o[0] += p0.x * wm;  o[1] += p0.y * wm;
            o[2] += p0.z * wm;  o[3] += p0.w * wm;
            o[4] += p1.x * wm;  o[5] += p1.y * wm;
            o[6] += p1.z * wm;  o[7] += p1.w * wm;
        }
#pragma unroll
        for (int t = 0; t < WPB; t++) out[(w0 + t) * OUT + h] = o[t];
    }
}

// ---------------- launch (minimal-node fork-join) ----------------
static cudaStream_t s1;
static cudaEvent_t evRoot, evF;
static bool g_host_init = false;

extern "C" void kernel_launch(void* const* d_in, const int* in_sizes, int n_in,
                              void* d_out, int out_size)
{
    if (!g_host_init) {
        cudaStreamCreateWithFlags(&s1, cudaStreamNonBlocking);
        cudaEventCreateWithFlags(&evRoot, cudaEventDisableTiming);
        cudaEventCreateWithFlags(&evF, cudaEventDisableTiming);
        g_host_init = true;
    }

    const float* cell_x  = (const float*)d_in[0];
    const float* well_x  = (const float*)d_in[1];
    const int*   ei_cell = (const int*)  d_in[2];
    const int*   ews     = (const int*)  d_in[3];
    const int*   ewd     = (const int*)  d_in[4];
    const float* W_cell  = (const float*)d_in[5];
    const float* b_cell  = (const float*)d_in[6];
    const float* W_well  = (const float*)d_in[7];
    const float* b_well  = (const float*)d_in[8];
    const float* Wl_cc   = (const float*)d_in[9];
    const float* bl_cc   = (const float*)d_in[10];
    const float* Wr_cc   = (const float*)d_in[11];
    const float* Wl_cw   = (const float*)d_in[12];
    const float* bl_cw   = (const float*)d_in[13];
    const float* Wr_cw   = (const float*)d_in[14];
    const float* W_m1    = (const float*)d_in[15];
    const float* b_m1    = (const float*)d_in[16];
    const float* W_m2    = (const float*)d_in[17];
    const float* b_m2    = (const float*)d_in[18];
    float* out = (float*)d_out;

    // fork: fuse chain on side stream (only k_well consumes g_F)
    cudaEventRecord(evRoot, 0);
    cudaStreamWaitEvent(s1, evRoot, 0);
    k_fuse<<<43, 256, 0, s1>>>(W_cell, b_cell, Wl_cc, Wr_cc, bl_cc,
                               W_well, b_well, Wl_cw, bl_cw, Wr_cw,
                               W_m1, b_m1);
    cudaEventRecord(evF, s1);

    // main stream: critical path
    k_zero_all<<<(N_CELL * CF / 4 + 255) / 256, 256>>>();
    k_mark<<<(E_CW + 255) / 256, 256>>>(ews);
    k_cc<<<(E_CC / 2 + 255) / 256, 256>>>(ei_cell, cell_x);
    k_cw<<<(E_CW + 255) / 256, 256>>>(ews, ewd, cell_x);
    cudaStreamWaitEvent(0, evF, 0);
    k_well<<<N_WELL / WPB, H>>>(well_x, W_m2, b_m2, out);
}